// round 5
// baseline (speedup 1.0000x reference)
#include <cuda_runtime.h>
#include <math.h>

#define DIM    1024
#define HALF   512
#define NMAX   65536
#define P2B    512          // pass2 blocks
#define P2ROWS 128          // rows per pass2 block
#define NB     128          // blocks for pre/post (grid-barrier kernels)

// ---------------- scratch (device globals) ----------------------------------------
__device__ float    g_qpart[NB * HALF];      // Wq GEMV partials
__device__ float    g_qk[DIM];               // Wk @ q
__device__ float    g_s[NMAX];               // raw scores
__device__ float    g_invn[NMAX];            // 1/||k_init[n]||
__device__ double   g_spart[128];            // [0:64) sum, [64:128) sumsq
__device__ float    g_epart[P2B];            // per-pass2-block exp sums
__device__ float    g_zpart[P2B * DIM];      // pass2 partial row-sums
__device__ float    g_vpart[NB * DIM];       // z@Wv partials
__device__ float    g_mpart[NB * DIM];       // ctx@Wm partials
__device__ unsigned g_sync = 0;              // generation-based grid barrier

// ---------------- grid barrier: 128 resident blocks, volatile-poll -----------------
__device__ __forceinline__ void grid_sync128() {
    __syncthreads();
    if (threadIdx.x == 0) {
        __threadfence();
        unsigned old = atomicAdd(&g_sync, 1u);
        unsigned target = (old / (unsigned)NB + 1u) * (unsigned)NB;
        while (*(volatile unsigned*)&g_sync < target) { }
        __threadfence();
    }
    __syncthreads();
}

// ---------------- kernel 1: q-norm + Wq GEMV + Wk GEMV (128 blocks x 256 thr) -----
__global__ void kern_pre(const float* __restrict__ q_init,
                         const float* __restrict__ Wq,
                         const float* __restrict__ Wk,
                         const float* __restrict__ bq) {
    __shared__ float qn_s[DIM];
    __shared__ float qs[HALF];
    __shared__ float red[8];
    int b = blockIdx.x, t = threadIdx.x, w = t >> 5, l = t & 31;

    if (b == 0 && t < 128) g_spart[t] = 0.0;   // reset stats each replay

    // redundant q l2norm per block (4 KB read, L2 hit)
    float4 v = ((const float4*)q_init)[t];
    float ss = v.x * v.x + v.y * v.y + v.z * v.z + v.w * v.w;
    #pragma unroll
    for (int o = 16; o; o >>= 1) ss += __shfl_xor_sync(0xFFFFFFFFu, ss, o);
    if (l == 0) red[w] = ss;
    __syncthreads();
    if (t == 0) {
        float tot = 0.f;
        #pragma unroll
        for (int i = 0; i < 8; i++) tot += red[i];
        red[0] = 1.0f / fmaxf(sqrtf(tot), 1e-12f);
    }
    __syncthreads();
    float inv = red[0];
    ((float4*)qn_s)[t] = make_float4(v.x * inv, v.y * inv, v.z * inv, v.w * inv);
    __syncthreads();

    // Wq GEMV partial: block b owns d-rows [b*8, b*8+8)
    {
        const float* W = Wq + (size_t)b * 8 * HALF;
        float a0 = 0.f, a1 = 0.f;
        #pragma unroll
        for (int d = 0; d < 8; d++) {
            float x = qn_s[b * 8 + d];
            a0 += x * W[d * HALF + t];
            a1 += x * W[d * HALF + t + 256];
        }
        g_qpart[b * HALF + t]       = a0;
        g_qpart[b * HALF + t + 256] = a1;
    }

    grid_sync128();

    // combine q = bq + sum(partials)
    #pragma unroll
    for (int j = 0; j < 2; j++) {
        int c = t + j * 256;
        float acc = bq[c];
        #pragma unroll 16
        for (int p = 0; p < NB; p++) acc += g_qpart[p * HALF + c];
        qs[c] = acc;
    }
    __syncthreads();

    // Wk GEMV: block b owns qk rows [b*8, b*8+8); one row per warp
    {
        int d = b * 8 + w;
        const float4* row = (const float4*)(Wk + (size_t)d * HALF);
        const float4* q4  = (const float4*)qs;
        float acc = 0.f;
        #pragma unroll
        for (int i = 0; i < 4; i++) {
            float4 vv = row[i * 32 + l];
            float4 qq = q4[i * 32 + l];
            acc += vv.x * qq.x + vv.y * qq.y + vv.z * qq.z + vv.w * qq.w;
        }
        #pragma unroll
        for (int o = 16; o; o >>= 1) acc += __shfl_xor_sync(0xFFFFFFFFu, acc, o);
        if (l == 0) g_qk[d] = acc;
    }
}

// ---------------- kernel 2: pass 1 over k_init (N/8 blocks x 256 thr) --------------
// default cache policy: the tail of K stays resident in L2 for pass 2
__global__ void kern_pass1(const float* __restrict__ Kmat) {
    __shared__ float qk_s[DIM];
    __shared__ float sc[8];
    int t = threadIdx.x;
    #pragma unroll
    for (int i = 0; i < 4; i++) qk_s[t + i * 256] = g_qk[t + i * 256];
    __syncthreads();
    int w = t >> 5, l = t & 31;
    long n = (long)blockIdx.x * 8 + w;
    const float4* row = (const float4*)(Kmat + n * DIM);
    const float4* q4  = (const float4*)qk_s;
    float ss = 0.f, dp = 0.f;
    #pragma unroll
    for (int i = 0; i < 8; i++) {
        float4 v = row[i * 32 + l];
        float4 q = q4[i * 32 + l];
        ss += v.x * v.x + v.y * v.y + v.z * v.z + v.w * v.w;
        dp += v.x * q.x + v.y * q.y + v.z * q.z + v.w * q.w;
    }
    #pragma unroll
    for (int o = 16; o; o >>= 1) {
        ss += __shfl_xor_sync(0xFFFFFFFFu, ss, o);
        dp += __shfl_xor_sync(0xFFFFFFFFu, dp, o);
    }
    if (l == 0) {
        float inv = 1.0f / fmaxf(sqrtf(ss), 1e-12f);
        float s = dp * inv;
        g_invn[n] = inv;
        g_s[n] = s;
        sc[w] = s;
    }
    __syncthreads();
    if (t == 0) {
        double a = 0.0, b2 = 0.0;
        #pragma unroll
        for (int i = 0; i < 8; i++) {
            double x = (double)sc[i];
            a += x; b2 += x * x;
        }
        int slot = blockIdx.x & 63;
        atomicAdd(&g_spart[slot], a);
        atomicAdd(&g_spart[64 + slot], b2);
    }
}

// ---------------- kernel 3: pass 2 with fused exp (P2B blocks x 256 thr) -----------
// iterates rows in REVERSE so the freshest L2-resident tail of K is consumed first
__global__ void kern_pass2(const float* __restrict__ Kmat, int N) {
    __shared__ float ws[P2ROWS];
    __shared__ float st[2];    // mean, rstd
    __shared__ float red[8];
    int t = threadIdx.x, w = t >> 5, l = t & 31;
    long n0 = (long)(P2B - 1 - blockIdx.x) * P2ROWS;

    // finalize stats (redundant per block; 128 doubles, L2 hit)
    if (t < 32) {
        double a  = g_spart[t]      + g_spart[t + 32];
        double b2 = g_spart[64 + t] + g_spart[96 + t];
        #pragma unroll
        for (int o = 16; o; o >>= 1) {
            a  += __shfl_xor_sync(0xFFFFFFFFu, a, o);
            b2 += __shfl_xor_sync(0xFFFFFFFFu, b2, o);
        }
        if (t == 0) {
            double mean = a / N;
            double var  = (b2 - (double)N * mean * mean) / (double)(N - 1);
            double sd   = sqrt(var > 0.0 ? var : 0.0);
            st[0] = (float)mean;
            st[1] = (float)(1.0 / (sd + 1e-8));
        }
    }
    __syncthreads();
    float mean = st[0], rstd = st[1];

    // this block's 128 weights: w = exp(clip(zscore)) * invn ; e-sum to g_epart
    float e = 0.f;
    if (t < P2ROWS) {
        float s   = g_s[n0 + t];
        float inv = g_invn[n0 + t];
        float x = fminf(fmaxf((s - mean) * rstd, -10.f), 10.f);
        e = expf(x);
        ws[t] = e * inv;
    }
    #pragma unroll
    for (int o = 16; o; o >>= 1) e += __shfl_xor_sync(0xFFFFFFFFu, e, o);
    if (l == 0) red[w] = e;
    __syncthreads();
    if (t == 0) {
        float tot = 0.f;
        #pragma unroll
        for (int i = 0; i < 4; i++) tot += red[i];   // warps 4..7 hold zeros
        g_epart[blockIdx.x] = tot;
    }
    __syncthreads();

    // weighted row-sum partials (1/denom deferred to kern_post)
    float4 acc = make_float4(0.f, 0.f, 0.f, 0.f);
    const float4* base = (const float4*)Kmat + n0 * (DIM / 4) + t;
    #pragma unroll 8
    for (int r = 0; r < P2ROWS; r++) {
        float wv = ws[r];
        float4 v = base[(long)r * (DIM / 4)];
        acc.x += wv * v.x;
        acc.y += wv * v.y;
        acc.z += wv * v.z;
        acc.w += wv * v.w;
    }
    ((float4*)g_zpart)[blockIdx.x * (DIM / 4) + t] = acc;
}

// ---------------- kernel 4: z-reduce + Wv GEMV + Wm GEMV + gate (128 x 256) --------
__global__ void kern_post(const float* __restrict__ Wv,
                          const float* __restrict__ Wm,
                          const float* __restrict__ bv,
                          const float* __restrict__ bm,
                          const float* __restrict__ q_init,
                          const float* __restrict__ gamma,
                          float* __restrict__ out) {
    __shared__ float cred[8][33];
    __shared__ float xs[8];
    __shared__ float red[8];
    __shared__ float invden_s;
    int b = blockIdx.x, t = threadIdx.x, w = t >> 5, l = t & 31;
    int j = t & 7, g = t >> 3;   // 8 cols x 32 groups

    // denom = sum of 512 e-partials (redundant per block)
    {
        float d = g_epart[t] + g_epart[t + 256];
        #pragma unroll
        for (int o = 16; o; o >>= 1) d += __shfl_xor_sync(0xFFFFFFFFu, d, o);
        if (l == 0) red[w] = d;
        __syncthreads();
        if (t == 0) {
            float tot = 0.f;
            #pragma unroll
            for (int i = 0; i < 8; i++) tot += red[i];
            invden_s = 1.0f / tot;
        }
        __syncthreads();
    }
    float invden = invden_s;

    // z slice for cols [b*8, b*8+8): reduce 512 zparts (16 per thread)
    {
        float a = 0.f;
        #pragma unroll
        for (int k = 0; k < 16; k++)
            a += g_zpart[(g * 16 + k) * DIM + b * 8 + j];
        cred[j][g] = a;
        __syncthreads();
        if (t < 8) {
            float s = 0.f;
            #pragma unroll
            for (int i = 0; i < 32; i++) s += cred[t][i];
            xs[t] = s * invden;
        }
        __syncthreads();
    }

    // Wv GEMV partial from z slice (8 d-rows)
    {
        const float4* W4 = (const float4*)(Wv + (size_t)b * 8 * DIM) + t;
        float4 acc = make_float4(0.f, 0.f, 0.f, 0.f);
        #pragma unroll
        for (int d = 0; d < 8; d++) {
            float xv = xs[d];
            float4 v = W4[d * (DIM / 4)];
            acc.x += xv * v.x;
            acc.y += xv * v.y;
            acc.z += xv * v.z;
            acc.w += xv * v.w;
        }
        ((float4*)g_vpart)[b * (DIM / 4) + t] = acc;
    }

    grid_sync128();

    // ctx slice: bv + reduce of 128 v-partials over cols [b*8, b*8+8)
    {
        float a = 0.f;
        #pragma unroll
        for (int k = 0; k < 4; k++)
            a += g_vpart[(g * 4 + k) * DIM + b * 8 + j];
        cred[j][g] = a;
        __syncthreads();
        if (t < 8) {
            float s = bv[b * 8 + t];
            #pragma unroll
            for (int i = 0; i < 32; i++) s += cred[t][i];
            xs[t] = s;
        }
        __syncthreads();
    }

    // Wm GEMV partial from ctx slice
    {
        const float4* W4 = (const float4*)(Wm + (size_t)b * 8 * DIM) + t;
        float4 acc = make_float4(0.f, 0.f, 0.f, 0.f);
        #pragma unroll
        for (int d = 0; d < 8; d++) {
            float xv = xs[d];
            float4 v = W4[d * (DIM / 4)];
            acc.x += xv * v.x;
            acc.y += xv * v.y;
            acc.z += xv * v.z;
            acc.w += xv * v.w;
        }
        ((float4*)g_mpart)[b * (DIM / 4) + t] = acc;
    }

    grid_sync128();

    // final gate for out cols [b*8, b*8+8)
    {
        float a = 0.f;
        #pragma unroll
        for (int k = 0; k < 4; k++)
            a += g_mpart[(g * 4 + k) * DIM + b * 8 + j];
        cred[j][g] = a;
        __syncthreads();
        if (t < 8) {
            int c = b * 8 + t;
            float s = bm[c];
            #pragma unroll
            for (int i = 0; i < 32; i++) s += cred[t][i];
            float gg = 1.0f / (1.0f + expf(-gamma[0]));
            out[c] = gg * q_init[c] + (1.0f - gg) * s;
        }
    }
}

// ---------------- launcher ----------------------------------------------------------
extern "C" void kernel_launch(void* const* d_in, const int* in_sizes, int n_in,
                              void* d_out, int out_size) {
    const float* q_init = (const float*)d_in[0];
    const float* k_init = (const float*)d_in[1];
    const float* Wq     = (const float*)d_in[2];
    const float* bq     = (const float*)d_in[3];
    const float* Wk     = (const float*)d_in[4];
    // d_in[5] = bk: cancels under z-score normalization of scores
    const float* Wv     = (const float*)d_in[6];
    const float* bv     = (const float*)d_in[7];
    const float* Wm     = (const float*)d_in[8];
    const float* bm     = (const float*)d_in[9];
    const float* gamma  = (const float*)d_in[10];
    float* out = (float*)d_out;

    int N = in_sizes[1] / DIM;  // 65536

    kern_pre  <<<NB, 256>>>(q_init, Wq, Wk, bq);
    kern_pass1<<<N / 8, 256>>>(k_init);
    kern_pass2<<<P2B, 256>>>(k_init, N);
    kern_post <<<NB, 256>>>(Wv, Wm, bv, bm, q_init, gamma, out);
}

// round 6
// speedup vs baseline: 1.0601x; 1.0601x over previous
#include <cuda_runtime.h>
#include <math.h>

#define DIM    1024
#define HALF   512
#define NMAX   65536
#define P2B    512          // pass2 blocks
#define P2ROWS 128          // rows per pass2 block
#define NBPRE  64           // pre blocks
#define NBPOST 128          // post blocks

// ---------------- scratch (device globals) ----------------------------------------
__device__ float    g_qpart[NBPRE * HALF];   // Wq GEMV partials
__device__ float    g_qk[DIM];               // Wk @ q
__device__ float    g_s[NMAX];               // raw scores
__device__ float    g_invn[NMAX];            // 1/||k_init[n]||
__device__ float    g_sfA[512];              // score-sum slots (float)
__device__ float    g_sfB[512];              // score-sumsq slots (float)
__device__ float    g_epart[P2B];            // per-pass2-block exp sums
__device__ float    g_zpart[P2B * DIM];      // pass2 partial row-sums
__device__ float    g_vpart[NBPOST * DIM];   // z@Wv partials
__device__ float    g_mpart[NBPOST * DIM];   // ctx@Wm partials
__device__ unsigned g_syncA = 0;             // barrier counter (pre)
__device__ unsigned g_syncB = 0;             // barrier counter (post)

// ---------------- generation-based grid barrier (all blocks resident) --------------
__device__ __forceinline__ void grid_sync(unsigned* ctr, unsigned nb) {
    __syncthreads();
    if (threadIdx.x == 0) {
        __threadfence();
        unsigned old = atomicAdd(ctr, 1u);
        unsigned target = (old / nb + 1u) * nb;
        while (*(volatile unsigned*)ctr < target) __nanosleep(64);
        __threadfence();
    }
    __syncthreads();
}

// ---------------- kernel 1: q-norm + Wq GEMV + Wk GEMV (64 blocks x 256 thr) ------
__global__ void kern_pre(const float* __restrict__ q_init,
                         const float* __restrict__ Wq,
                         const float* __restrict__ Wk,
                         const float* __restrict__ bq) {
    __shared__ float qn_s[DIM];
    __shared__ float qs[HALF];
    __shared__ float red[8];
    int b = blockIdx.x, t = threadIdx.x, w = t >> 5, l = t & 31;

    // reset stat slots each replay (64 blocks x 8 threads = 512)
    if (t < 8) {
        g_sfA[b * 8 + t] = 0.f;
        g_sfB[b * 8 + t] = 0.f;
    }

    // redundant q l2norm per block (4 KB read, L2 hit)
    float4 v = ((const float4*)q_init)[t];
    float ss = v.x * v.x + v.y * v.y + v.z * v.z + v.w * v.w;
    #pragma unroll
    for (int o = 16; o; o >>= 1) ss += __shfl_xor_sync(0xFFFFFFFFu, ss, o);
    if (l == 0) red[w] = ss;
    __syncthreads();
    if (t == 0) {
        float tot = 0.f;
        #pragma unroll
        for (int i = 0; i < 8; i++) tot += red[i];
        red[0] = 1.0f / fmaxf(sqrtf(tot), 1e-12f);
    }
    __syncthreads();
    float inv = red[0];
    ((float4*)qn_s)[t] = make_float4(v.x * inv, v.y * inv, v.z * inv, v.w * inv);
    __syncthreads();

    // Wq GEMV partial: block b owns d-rows [b*16, b*16+16)
    {
        const float* W = Wq + (size_t)b * 16 * HALF;
        float a0 = 0.f, a1 = 0.f;
        #pragma unroll
        for (int d = 0; d < 16; d++) {
            float x = qn_s[b * 16 + d];
            a0 += x * W[d * HALF + t];
            a1 += x * W[d * HALF + t + 256];
        }
        g_qpart[b * HALF + t]       = a0;
        g_qpart[b * HALF + t + 256] = a1;
    }

    grid_sync(&g_syncA, NBPRE);

    // combine q = bq + sum(partials)
    #pragma unroll
    for (int j = 0; j < 2; j++) {
        int c = t + j * 256;
        float acc = bq[c];
        #pragma unroll 16
        for (int p = 0; p < NBPRE; p++) acc += g_qpart[p * HALF + c];
        qs[c] = acc;
    }
    __syncthreads();

    // Wk GEMV: block b owns qk rows [b*16, b*16+16); 8 warps x 2 rows
    #pragma unroll
    for (int r = 0; r < 2; r++) {
        int d = b * 16 + w * 2 + r;
        const float4* row = (const float4*)(Wk + (size_t)d * HALF);
        const float4* q4  = (const float4*)qs;
        float acc = 0.f;
        #pragma unroll
        for (int i = 0; i < 4; i++) {
            float4 vv = row[i * 32 + l];
            float4 qq = q4[i * 32 + l];
            acc += vv.x * qq.x + vv.y * qq.y + vv.z * qq.z + vv.w * qq.w;
        }
        #pragma unroll
        for (int o = 16; o; o >>= 1) acc += __shfl_xor_sync(0xFFFFFFFFu, acc, o);
        if (l == 0) g_qk[d] = acc;
    }
}

// ---------------- kernel 2: pass 1 over k_init (N/8 blocks x 256 thr) --------------
// stats via lane-0 atomics into 512 spread slots: no extra syncs, fast block retire
__global__ void kern_pass1(const float* __restrict__ Kmat) {
    __shared__ float qk_s[DIM];
    int t = threadIdx.x;
    #pragma unroll
    for (int i = 0; i < 4; i++) qk_s[t + i * 256] = g_qk[t + i * 256];
    __syncthreads();
    int w = t >> 5, l = t & 31;
    long n = (long)blockIdx.x * 8 + w;
    const float4* row = (const float4*)(Kmat + n * DIM);
    const float4* q4  = (const float4*)qk_s;
    float ss = 0.f, dp = 0.f;
    #pragma unroll
    for (int i = 0; i < 8; i++) {
        float4 v = row[i * 32 + l];
        float4 q = q4[i * 32 + l];
        ss += v.x * v.x + v.y * v.y + v.z * v.z + v.w * v.w;
        dp += v.x * q.x + v.y * q.y + v.z * q.z + v.w * q.w;
    }
    #pragma unroll
    for (int o = 16; o; o >>= 1) {
        ss += __shfl_xor_sync(0xFFFFFFFFu, ss, o);
        dp += __shfl_xor_sync(0xFFFFFFFFu, dp, o);
    }
    if (l == 0) {
        float inv = 1.0f / fmaxf(sqrtf(ss), 1e-12f);
        float s = dp * inv;
        g_invn[n] = inv;
        g_s[n] = s;
        int slot = (int)(n & 511);
        atomicAdd(&g_sfA[slot], s);
        atomicAdd(&g_sfB[slot], s * s);
    }
}

// ---------------- kernel 3: pass 2 with fused exp (P2B blocks x 256 thr) -----------
// reversed row order: consume the L2-resident tail of K left by pass 1 first
__global__ void kern_pass2(const float* __restrict__ Kmat, int N) {
    __shared__ float ws[P2ROWS];
    __shared__ float st[2];    // mean, rstd
    __shared__ float redA[8];
    __shared__ float redB[8];
    int t = threadIdx.x, w = t >> 5, l = t & 31;
    long n0 = (long)(P2B - 1 - blockIdx.x) * P2ROWS;

    // finalize stats (redundant per block; 4 KB of L2-hit reads)
    {
        float sa = g_sfA[t] + g_sfA[t + 256];
        float sb = g_sfB[t] + g_sfB[t + 256];
        #pragma unroll
        for (int o = 16; o; o >>= 1) {
            sa += __shfl_xor_sync(0xFFFFFFFFu, sa, o);
            sb += __shfl_xor_sync(0xFFFFFFFFu, sb, o);
        }
        if (l == 0) { redA[w] = sa; redB[w] = sb; }
        __syncthreads();
        if (t == 0) {
            float A = 0.f, B = 0.f;
            #pragma unroll
            for (int i = 0; i < 8; i++) { A += redA[i]; B += redB[i]; }
            double mean = (double)A / N;
            double var  = ((double)B - (double)N * mean * mean) / (double)(N - 1);
            double sd   = sqrt(var > 0.0 ? var : 0.0);
            st[0] = (float)mean;
            st[1] = (float)(1.0 / (sd + 1e-8));
        }
        __syncthreads();
    }
    float mean = st[0], rstd = st[1];

    // this block's 128 weights: w = exp(clip(zscore)) * invn ; e-sum to g_epart
    float e = 0.f;
    if (t < P2ROWS) {
        float s   = g_s[n0 + t];
        float inv = g_invn[n0 + t];
        float x = fminf(fmaxf((s - mean) * rstd, -10.f), 10.f);
        e = expf(x);
        ws[t] = e * inv;
    }
    #pragma unroll
    for (int o = 16; o; o >>= 1) e += __shfl_xor_sync(0xFFFFFFFFu, e, o);
    if (l == 0) redA[w] = e;
    __syncthreads();
    if (t == 0) {
        float tot = 0.f;
        #pragma unroll
        for (int i = 0; i < 4; i++) tot += redA[i];   // warps 4..7 hold zeros
        g_epart[blockIdx.x] = tot;
    }
    __syncthreads();

    // weighted row-sum partials (1/denom deferred to kern_post)
    float4 acc = make_float4(0.f, 0.f, 0.f, 0.f);
    const float4* base = (const float4*)Kmat + n0 * (DIM / 4) + t;
    #pragma unroll 8
    for (int r = 0; r < P2ROWS; r++) {
        float wv = ws[r];
        float4 v = base[(long)r * (DIM / 4)];
        acc.x += wv * v.x;
        acc.y += wv * v.y;
        acc.z += wv * v.z;
        acc.w += wv * v.w;
    }
    ((float4*)g_zpart)[blockIdx.x * (DIM / 4) + t] = acc;
}

// ---------------- kernel 4: z-reduce + Wv GEMV + Wm GEMV + gate (128 x 256) --------
__global__ void kern_post(const float* __restrict__ Wv,
                          const float* __restrict__ Wm,
                          const float* __restrict__ bv,
                          const float* __restrict__ bm,
                          const float* __restrict__ q_init,
                          const float* __restrict__ gamma,
                          float* __restrict__ out) {
    __shared__ float cred[8][33];
    __shared__ float xs[8];
    __shared__ float red[8];
    __shared__ float invden_s;
    int b = blockIdx.x, t = threadIdx.x, w = t >> 5, l = t & 31;
    int j = t & 7, g = t >> 3;   // 8 cols x 32 groups

    // fused phase: denom partials + z-partial reduction in one load window
    {
        float e2 = g_epart[t] + g_epart[t + 256];
        float a = 0.f;
        #pragma unroll
        for (int k = 0; k < 16; k++)
            a += g_zpart[(g * 16 + k) * DIM + b * 8 + j];
        #pragma unroll
        for (int o = 16; o; o >>= 1) e2 += __shfl_xor_sync(0xFFFFFFFFu, e2, o);
        if (l == 0) red[w] = e2;
        cred[j][g] = a;
        __syncthreads();
        if (t == 0) {
            float tot = 0.f;
            #pragma unroll
            for (int i = 0; i < 8; i++) tot += red[i];
            invden_s = 1.0f / tot;
        }
        if (t < 8) {
            float s = 0.f;
            #pragma unroll
            for (int i = 0; i < 32; i++) s += cred[t][i];
            xs[t] = s;            // invden folded into GEMV below
        }
        __syncthreads();
    }
    float invden = invden_s;

    // Wv GEMV partial from z slice (8 d-rows), invden folded in
    {
        const float4* W4 = (const float4*)(Wv + (size_t)b * 8 * DIM) + t;
        float4 acc = make_float4(0.f, 0.f, 0.f, 0.f);
        #pragma unroll
        for (int d = 0; d < 8; d++) {
            float xv = xs[d] * invden;
            float4 v = W4[d * (DIM / 4)];
            acc.x += xv * v.x;
            acc.y += xv * v.y;
            acc.z += xv * v.z;
            acc.w += xv * v.w;
        }
        ((float4*)g_vpart)[b * (DIM / 4) + t] = acc;
    }

    grid_sync(&g_syncB, NBPOST);

    // ctx slice: bv + reduce of 128 v-partials over cols [b*8, b*8+8)
    {
        float a = 0.f;
        #pragma unroll
        for (int k = 0; k < 4; k++)
            a += g_vpart[(g * 4 + k) * DIM + b * 8 + j];
        cred[j][g] = a;
        __syncthreads();
        if (t < 8) {
            float s = bv[b * 8 + t];
            #pragma unroll
            for (int i = 0; i < 32; i++) s += cred[t][i];
            xs[t] = s;
        }
        __syncthreads();
    }

    // Wm GEMV partial from ctx slice
    {
        const float4* W4 = (const float4*)(Wm + (size_t)b * 8 * DIM) + t;
        float4 acc = make_float4(0.f, 0.f, 0.f, 0.f);
        #pragma unroll
        for (int d = 0; d < 8; d++) {
            float xv = xs[d];
            float4 v = W4[d * (DIM / 4)];
            acc.x += xv * v.x;
            acc.y += xv * v.y;
            acc.z += xv * v.z;
            acc.w += xv * v.w;
        }
        ((float4*)g_mpart)[b * (DIM / 4) + t] = acc;
    }

    grid_sync(&g_syncB, NBPOST);

    // final gate for out cols [b*8, b*8+8)
    {
        float a = 0.f;
        #pragma unroll
        for (int k = 0; k < 4; k++)
            a += g_mpart[(g * 4 + k) * DIM + b * 8 + j];
        cred[j][g] = a;
        __syncthreads();
        if (t < 8) {
            int c = b * 8 + t;
            float s = bm[c];
            #pragma unroll
            for (int i = 0; i < 32; i++) s += cred[t][i];
            float gg = 1.0f / (1.0f + expf(-gamma[0]));
            out[c] = gg * q_init[c] + (1.0f - gg) * s;
        }
    }
}

// ---------------- launcher ----------------------------------------------------------
extern "C" void kernel_launch(void* const* d_in, const int* in_sizes, int n_in,
                              void* d_out, int out_size) {
    const float* q_init = (const float*)d_in[0];
    const float* k_init = (const float*)d_in[1];
    const float* Wq     = (const float*)d_in[2];
    const float* bq     = (const float*)d_in[3];
    const float* Wk     = (const float*)d_in[4];
    // d_in[5] = bk: cancels under z-score normalization of scores
    const float* Wv     = (const float*)d_in[6];
    const float* bv     = (const float*)d_in[7];
    const float* Wm     = (const float*)d_in[8];
    const float* bm     = (const float*)d_in[9];
    const float* gamma  = (const float*)d_in[10];
    float* out = (float*)d_out;

    int N = in_sizes[1] / DIM;  // 65536

    kern_pre  <<<NBPRE, 256>>>(q_init, Wq, Wk, bq);
    kern_pass1<<<N / 8, 256>>>(k_init);
    kern_pass2<<<P2B, 256>>>(k_init, N);
    kern_post <<<NBPOST, 256>>>(Wv, Wm, bv, bm, q_init, gamma, out);
}